// round 7
// baseline (speedup 1.0000x reference)
#include <cuda_runtime.h>

// LinearMPO: out[l, a*CHI+x, i, b*CHI+y] = sum_j cores[l,a,i,j,b] * mps[l,x,j,y]
// L=32, D=4, d=2, CHI=256.
// mps:   [32,256,2,256] f32   cores: [32,4,2,2,4] f32   out: [32,1024,2,1024] f32
//
// R3: 46.7us kernel, DRAM 59.7%, L1 64% (max pipe), issue 12.5%.
// R4: .cs hints NEUTRAL -> L2 policy not binding.
// R5/R6: v8.f32 PTX kernel failed container twice -> suspected GPU-host nvcc
//        can't compile PTX ISA 8.7 ops. De-risked: keep the balanced
//        single-wave grid (1024x128, 2 items/warp, zero tail), revert to
//        float4 loads/stores with .cs hints.

#define CHI_ 256

__global__ __launch_bounds__(128)
void mpo_mps_kernel(const float* __restrict__ mps,
                    const float* __restrict__ cores,
                    float* __restrict__ out)
{
    // Stage the entire cores tensor (8KB) in shared memory once per block.
    __shared__ float sc[2048];
    #pragma unroll
    for (int i = threadIdx.x; i < 2048; i += 128) sc[i] = cores[i];
    __syncthreads();

    const int warp_g = (blockIdx.x << 2) + (threadIdx.x >> 5);  // 0..4095
    const int lane   = threadIdx.x & 31;

    // Each warp handles items warp_g and warp_g + 4096 (of 8192 (l,x) pairs).
    #pragma unroll
    for (int it = 0; it < 2; ++it) {
        const int item = warp_g + it * 4096;
        const int l = item >> 8;         // / 256
        const int x = item & 255;

        // Two physical rows of mps for (l,x). Each lane covers y[lane*8 .. +8)
        // as two float4s (contiguous 1024B per warp per access -> coalesced).
        const float4* mrow = reinterpret_cast<const float4*>(
            mps + ((size_t)(l * CHI_ + x) * 2) * CHI_) + lane * 2;
        const float4 m0a = __ldcs(mrow + 0);
        const float4 m0b = __ldcs(mrow + 1);
        const float4 m1a = __ldcs(mrow + 64);      // +CHI_ floats = +64 float4
        const float4 m1b = __ldcs(mrow + 65);

        float* obase = out + (size_t)l * 2097152 + (size_t)x * 2048 + lane * 8;
        const float* c = sc + l * 64;

        #pragma unroll
        for (int a = 0; a < 4; ++a) {
            #pragma unroll
            for (int i = 0; i < 2; ++i) {
                #pragma unroll
                for (int b = 0; b < 4; ++b) {
                    const float c0 = c[a * 16 + i * 8 + 0 + b];  // j=0
                    const float c1 = c[a * 16 + i * 8 + 4 + b];  // j=1
                    float4 ra, rb;
                    ra.x = fmaf(c0, m0a.x, c1 * m1a.x);
                    ra.y = fmaf(c0, m0a.y, c1 * m1a.y);
                    ra.z = fmaf(c0, m0a.z, c1 * m1a.z);
                    ra.w = fmaf(c0, m0a.w, c1 * m1a.w);
                    rb.x = fmaf(c0, m0b.x, c1 * m1b.x);
                    rb.y = fmaf(c0, m0b.y, c1 * m1b.y);
                    rb.z = fmaf(c0, m0b.z, c1 * m1b.z);
                    rb.w = fmaf(c0, m0b.w, c1 * m1b.w);
                    float4* op = reinterpret_cast<float4*>(
                        obase + (size_t)a * 524288 + (size_t)i * 1024 + (size_t)b * CHI_);
                    __stcs(op + 0, ra);
                    __stcs(op + 1, rb);
                }
            }
        }
    }
}

extern "C" void kernel_launch(void* const* d_in, const int* in_sizes, int n_in,
                              void* d_out, int out_size)
{
    const float* mps   = (const float*)d_in[0];
    const float* cores = (const float*)d_in[1];
    // Defensive: identify by element count (mps=4194304, cores=2048).
    if (n_in >= 2 && in_sizes[0] == 2048) {
        const float* t = mps; mps = cores; cores = t;
    }
    float* out = (float*)d_out;

    mpo_mps_kernel<<<1024, 128>>>(mps, cores, out);
}

// round 8
// speedup vs baseline: 1.7382x; 1.7382x over previous
#include <cuda_runtime.h>

// LinearMPO: out[l, a*CHI+x, i, b*CHI+y] = sum_j cores[l,a,i,j,b] * mps[l,x,j,y]
// L=32, D=4, d=2, CHI=256.
// mps: [32,256,2,256] f32  cores: [32,4,2,2,4] f32  out: [32,1024,2,1024] f32
//
// History:
//  R3 46.7us: DRAM 59.7%, L1 64%, occ 52.7% (2048x256, 32 f4-stores/thread)
//  R4 .cs hints: NEUTRAL
//  R6 1024x128 (64 stores/warp-item): 82us REGRESSION -> store-MLP bound;
//     parallelism is load-bearing.
//  R8: 2x warps of R3, half the stores per thread. 4096 blocks x 256 thr;
//     each thread: 1 (l,x,ygroup4), 16 (a,i,b) combos (split by a-half).

#define CHI_ 256

__global__ __launch_bounds__(256)
void mpo_mps_kernel(const float* __restrict__ mps,
                    const float* __restrict__ cores,
                    float* __restrict__ out)
{
    // Block owns 2 consecutive x at one l (2 | 256 so l is uniform per block).
    const int blk = blockIdx.x;          // 0..4095
    const int l   = blk >> 7;            // 128 blocks per l
    const int tid = threadIdx.x;
    const int x   = ((blk & 127) << 1) + (tid >> 7);  // which of 2 x
    const int r   = tid & 127;
    const int ah  = r >> 6;              // a-half: a in {0,1} or {2,3}
    const int ty  = r & 63;              // float4 group along y

    // Stage this site's 64 core coefficients (broadcast reads).
    __shared__ float sc[64];
    if (tid < 64) sc[tid] = cores[l * 64 + tid];
    __syncthreads();

    // Two physical rows of mps for (l,x); this thread's float4 of each.
    const float4* m0p = reinterpret_cast<const float4*>(
        mps + ((size_t)(l * CHI_ + x) * 2 + 0) * CHI_);
    const float4* m1p = reinterpret_cast<const float4*>(
        mps + ((size_t)(l * CHI_ + x) * 2 + 1) * CHI_);
    const float4 m0 = __ldcs(m0p + ty);
    const float4 m1 = __ldcs(m1p + ty);

    const size_t lbase = (size_t)l * 2097152      // l * D*CHI*d*D*CHI
                       + (size_t)x * 2048         // x * d*D*CHI
                       + (size_t)ty * 4;

    #pragma unroll
    for (int aa = 0; aa < 2; ++aa) {
        const int a = (ah << 1) + aa;
        #pragma unroll
        for (int i = 0; i < 2; ++i) {
            #pragma unroll
            for (int b = 0; b < 4; ++b) {
                const float c0 = sc[a * 16 + i * 8 + 0 + b];   // j=0
                const float c1 = sc[a * 16 + i * 8 + 4 + b];   // j=1
                float4 v;
                v.x = fmaf(c0, m0.x, c1 * m1.x);
                v.y = fmaf(c0, m0.y, c1 * m1.y);
                v.z = fmaf(c0, m0.z, c1 * m1.z);
                v.w = fmaf(c0, m0.w, c1 * m1.w);
                const size_t off = lbase
                                 + (size_t)a * 524288   // a * CHI*d*D*CHI
                                 + (size_t)i * 1024     // i * D*CHI
                                 + (size_t)b * CHI_;
                __stcs(reinterpret_cast<float4*>(out + off), v);
            }
        }
    }
}

extern "C" void kernel_launch(void* const* d_in, const int* in_sizes, int n_in,
                              void* d_out, int out_size)
{
    const float* mps   = (const float*)d_in[0];
    const float* cores = (const float*)d_in[1];
    // Defensive: identify by element count (mps=4194304, cores=2048).
    if (n_in >= 2 && in_sizes[0] == 2048) {
        const float* t = mps; mps = cores; cores = t;
    }
    float* out = (float*)d_out;

    mpo_mps_kernel<<<4096, 256>>>(mps, cores, out);
}